// round 1
// baseline (speedup 1.0000x reference)
#include <cuda_runtime.h>
#include <math.h>

#define N_BOXES 256
#define N_VIEWS 6
#define P_TOT   (N_BOXES * N_VIEWS)   // 1536
#define C_FEAT  256
#define HF      116
#define WF      200
#define HW      (HF * WF)             // 23200
#define EPS     1e-8f

// Scratch (no dynamic allocation allowed)
__device__ int   g_u0[P_TOT];
__device__ int   g_v0[P_TOT];
__device__ int   g_valid[P_TOT];
__device__ int   g_first;
__device__ float g_stored[C_FEAT];
__device__ float g_stored_inv;
__device__ float g_loss[P_TOT];

// ---------------------------------------------------------------------------
// Kernel A: projection for all pairs, find first valid index, gather "stored"
// feature vector (4-pixel average at first pair) and its inverse norm.
// Single block of 256 threads.
// ---------------------------------------------------------------------------
__global__ void proj_kernel(const float* __restrict__ boxes,
                            const float* __restrict__ feats,
                            const float* __restrict__ Kmat,
                            const float* __restrict__ Tmat,
                            const int*   __restrict__ img_sizes)
{
    __shared__ int   s_first;
    __shared__ float s_red[256];
    const int tid = threadIdx.x;
    if (tid == 0) s_first = P_TOT;
    __syncthreads();

    for (int p = tid; p < P_TOT; p += blockDim.x) {
        const int n = p / N_VIEWS;
        const int v = p % N_VIEWS;
        const float cx = boxes[n * 7 + 0];
        const float cy = boxes[n * 7 + 1];
        const float cz = boxes[n * 7 + 2];

        const float* Tv = Tmat + v * 16;   // T[v] is 4x4 row-major
        const float pc0 = Tv[0] * cx + Tv[1] * cy + Tv[2]  * cz + Tv[3];
        const float pc1 = Tv[4] * cx + Tv[5] * cy + Tv[6]  * cz + Tv[7];
        const float pc2 = Tv[8] * cx + Tv[9] * cy + Tv[10] * cz + Tv[11];

        const float* Kv = Kmat + v * 9;    // K[v] is 3x3 row-major
        const float q0 = Kv[0] * pc0 + Kv[1] * pc1 + Kv[2] * pc2;
        const float q1 = Kv[3] * pc0 + Kv[4] * pc1 + Kv[5] * pc2;
        const float q2 = Kv[6] * pc0 + Kv[7] * pc1 + Kv[8] * pc2;

        const float z  = pc2;
        const float u  = q0 / q2;          // reference: u = p2d.x / p2d.z
        const float vv = q1 / z;           // reference: v = p2d.y / p_cam.z

        const float Himg = (float)img_sizes[v * 2 + 0];
        const float Wimg = (float)img_sizes[v * 2 + 1];
        const float u_s = u  * (float)WF / Wimg;
        const float v_s = vv * (float)HF / Himg;
        const int u0 = (int)floorf(u_s);
        const int v0 = (int)floorf(v_s);

        const bool valid = (z > 0.0f) && (u >= 0.0f) && (u < Wimg) &&
                           (vv >= 0.0f) && (vv < Himg) &&
                           (u0 < WF - 1) && (v0 < HF - 1);

        g_u0[p]    = min(max(u0, 0), WF - 2);
        g_v0[p]    = min(max(v0, 0), HF - 2);
        g_valid[p] = valid ? 1 : 0;
        if (valid) atomicMin(&s_first, p);
    }
    __syncthreads();

    const int first = (s_first == P_TOT) ? 0 : s_first;
    if (tid == 0) g_first = first;

    // Phase 2: gather stored = fm[first] (coords written above are visible
    // after __syncthreads within this block).
    const int u0f   = g_u0[first];
    const int v0f   = g_v0[first];
    const int viewf = first % N_VIEWS;
    const float* base = feats + (size_t)viewf * C_FEAT * HW + (size_t)v0f * WF + u0f;

    float sq = 0.0f;
    for (int c = tid; c < C_FEAT; c += blockDim.x) {
        const float* pch = base + (size_t)c * HW;
        const float fm = 0.25f * (pch[0] + pch[1] + pch[WF] + pch[WF + 1]);
        g_stored[c] = fm;
        sq += fm * fm;
    }
    s_red[tid] = sq;
    __syncthreads();
    #pragma unroll
    for (int s = 128; s > 0; s >>= 1) {
        if (tid < s) s_red[tid] += s_red[tid + s];
        __syncthreads();
    }
    if (tid == 0) g_stored_inv = 1.0f / fmaxf(sqrtf(s_red[0]), EPS);
}

// ---------------------------------------------------------------------------
// Kernel B: one warp per pair. Gather 4x256 channel-strided values, fused
// dot-with-stored + self-norm, write per-pair loss.
// ---------------------------------------------------------------------------
__global__ void loss_kernel(const float* __restrict__ feats)
{
    __shared__ float s_stored[C_FEAT];
    for (int c = threadIdx.x; c < C_FEAT; c += blockDim.x)
        s_stored[c] = g_stored[c];
    __syncthreads();

    const int warp = threadIdx.x >> 5;
    const int lane = threadIdx.x & 31;
    const int p = blockIdx.x * (blockDim.x >> 5) + warp;
    if (p >= P_TOT) return;

    if (!g_valid[p] || p == g_first) {
        if (lane == 0) g_loss[p] = 0.0f;
        return;
    }

    const int u0 = g_u0[p];
    const int v0 = g_v0[p];
    const int view = p % N_VIEWS;
    const float* base = feats + (size_t)view * C_FEAT * HW + (size_t)v0 * WF + u0;

    float dot = 0.0f, nrm = 0.0f;
    #pragma unroll
    for (int i = 0; i < C_FEAT / 32; i++) {
        const int c = lane + i * 32;
        const float* pch = base + (size_t)c * HW;
        const float fm = 0.25f * (pch[0] + pch[1] + pch[WF] + pch[WF + 1]);
        dot += fm * s_stored[c];
        nrm += fm * fm;
    }
    #pragma unroll
    for (int o = 16; o > 0; o >>= 1) {
        dot += __shfl_xor_sync(0xffffffffu, dot, o);
        nrm += __shfl_xor_sync(0xffffffffu, nrm, o);
    }
    if (lane == 0) {
        const float inv_i = 1.0f / fmaxf(sqrtf(nrm), EPS);
        g_loss[p] = 1.0f - dot * inv_i * g_stored_inv;
    }
}

// ---------------------------------------------------------------------------
// Kernel C: deterministic single-block reduction to the scalar output.
// ---------------------------------------------------------------------------
__global__ void finalize_kernel(float* __restrict__ out)
{
    __shared__ float s_sum[256];
    __shared__ int   s_cnt[256];
    const int tid = threadIdx.x;
    const int first = g_first;

    float total = 0.0f;
    int cnt = 0;
    for (int p = tid; p < P_TOT; p += 256) {
        if (g_valid[p] && p != first) { total += g_loss[p]; cnt++; }
    }
    s_sum[tid] = total;
    s_cnt[tid] = cnt;
    __syncthreads();
    #pragma unroll
    for (int s = 128; s > 0; s >>= 1) {
        if (tid < s) { s_sum[tid] += s_sum[tid + s]; s_cnt[tid] += s_cnt[tid + s]; }
        __syncthreads();
    }
    if (tid == 0) {
        const int n = s_cnt[0];
        out[0] = (n > 0) ? s_sum[0] / (float)max(n, 1) : 0.0f;
    }
}

// ---------------------------------------------------------------------------
extern "C" void kernel_launch(void* const* d_in, const int* in_sizes, int n_in,
                              void* d_out, int out_size)
{
    const float* boxes     = (const float*)d_in[0];  // (256, 7)
    const float* feats     = (const float*)d_in[1];  // (6, 256, 116, 200)
    const float* Kmat      = (const float*)d_in[2];  // (6, 3, 3)
    const float* Tmat      = (const float*)d_in[3];  // (6, 4, 4)
    const int*   img_sizes = (const int*)d_in[4];    // (6, 2)
    float* out = (float*)d_out;

    proj_kernel<<<1, 256>>>(boxes, feats, Kmat, Tmat, img_sizes);
    loss_kernel<<<(P_TOT + 7) / 8, 256>>>(feats);    // 192 blocks x 8 warps
    finalize_kernel<<<1, 256>>>(out);
}

// round 3
// speedup vs baseline: 1.3226x; 1.3226x over previous
#include <cuda_runtime.h>
#include <math.h>

#define N_BOXES 256
#define N_VIEWS 6
#define P_TOT   (N_BOXES * N_VIEWS)   // 1536
#define C_FEAT  256
#define HF      116
#define WF      200
#define HW      (HF * WF)             // 23200
#define EPS     1e-8f

#define NBLK    96                     // 96 blocks x 8 warps x 2 pairs = 1536
#define FSCALE  4294967296.0           // 2^32 fixed-point scale

// Deterministic cross-block accumulators (integer atomics only)
__device__ unsigned long long g_sum  = 0ULL;
__device__ int                g_cnt  = 0;
__device__ int                g_done = 0;

__global__ void __launch_bounds__(256, 1)
fused_kernel(const float* __restrict__ boxes,
             const float* __restrict__ feats,
             const float* __restrict__ Kmat,
             const float* __restrict__ Tmat,
             const int*   __restrict__ img_sizes,
             float*       __restrict__ out)
{
    __shared__ int   s_coord[P_TOT];      // u0c | v0c<<8 | valid<<31
    __shared__ int   s_first;
    __shared__ float s_stored[C_FEAT];
    __shared__ float s_red[256];
    __shared__ float s_sinv;
    __shared__ float s_loss[16];
    __shared__ int   s_lval[16];

    const int tid  = threadIdx.x;
    const int warp = tid >> 5;
    const int lane = tid & 31;

    if (tid == 0) s_first = P_TOT;
    __syncthreads();

    // ---- Phase 1: every block computes ALL projections (redundant, cheap) ----
    #pragma unroll
    for (int i = 0; i < P_TOT / 256; i++) {
        const int p = tid + i * 256;
        const int n = p / N_VIEWS;
        const int v = p - n * N_VIEWS;
        const float cx = boxes[n * 7 + 0];
        const float cy = boxes[n * 7 + 1];
        const float cz = boxes[n * 7 + 2];

        const float* Tv = Tmat + v * 16;   // 4x4 row-major
        const float pc0 = Tv[0] * cx + Tv[1] * cy + Tv[2]  * cz + Tv[3];
        const float pc1 = Tv[4] * cx + Tv[5] * cy + Tv[6]  * cz + Tv[7];
        const float pc2 = Tv[8] * cx + Tv[9] * cy + Tv[10] * cz + Tv[11];

        const float* Kv = Kmat + v * 9;    // 3x3 row-major
        const float q0 = Kv[0] * pc0 + Kv[1] * pc1 + Kv[2] * pc2;
        const float q1 = Kv[3] * pc0 + Kv[4] * pc1 + Kv[5] * pc2;
        const float q2 = Kv[6] * pc0 + Kv[7] * pc1 + Kv[8] * pc2;

        const float z  = pc2;
        const float u  = q0 / q2;          // ref: u = p2d.x / p2d.z
        const float vv = q1 / z;           // ref: v = p2d.y / p_cam.z

        const float Himg = (float)img_sizes[v * 2 + 0];
        const float Wimg = (float)img_sizes[v * 2 + 1];
        const float u_s = u  * (float)WF / Wimg;
        const float v_s = vv * (float)HF / Himg;
        const int u0 = (int)floorf(u_s);
        const int v0 = (int)floorf(v_s);

        const bool valid = (z > 0.0f) && (u >= 0.0f) && (u < Wimg) &&
                           (vv >= 0.0f) && (vv < Himg) &&
                           (u0 < WF - 1) && (v0 < HF - 1);

        const int u0c = min(max(u0, 0), WF - 2);
        const int v0c = min(max(v0, 0), HF - 2);
        s_coord[p] = u0c | (v0c << 8) | (valid ? (1 << 31) : 0);
        if (valid) atomicMin(&s_first, p);
    }
    __syncthreads();

    const int first = (s_first == P_TOT) ? 0 : s_first;

    // ---- Phase 2: gather 'stored' vector into smem (one channel per thread) ----
    {
        const int cf    = s_coord[first];
        const int u0f   = cf & 0xFF;
        const int v0f   = (cf >> 8) & 0xFF;
        const int viewf = first % N_VIEWS;
        const float* base = feats + (size_t)viewf * C_FEAT * HW
                                  + (size_t)v0f * WF + u0f;
        const float* pch = base + (size_t)tid * HW;
        const float fm = 0.25f * (pch[0] + pch[1] + pch[WF] + pch[WF + 1]);
        s_stored[tid] = fm;
        s_red[tid] = fm * fm;
    }
    __syncthreads();
    #pragma unroll
    for (int s = 128; s > 0; s >>= 1) {
        if (tid < s) s_red[tid] += s_red[tid + s];
        __syncthreads();
    }
    if (tid == 0) s_sinv = 1.0f / fmaxf(sqrtf(s_red[0]), EPS);
    __syncthreads();

    // ---- Phase 3: each warp processes 2 pairs ----
    #pragma unroll
    for (int j = 0; j < 2; j++) {
        const int p = (blockIdx.x * 8 + warp) * 2 + j;
        const int cp    = s_coord[p];
        const int valid = cp >> 31;        // arithmetic shift: -1 or 0
        float loss = 0.0f;
        int cnt = 0;
        if (valid && p != first) {
            const int u0   = cp & 0xFF;
            const int v0   = (cp >> 8) & 0xFF;
            const int view = p % N_VIEWS;
            const float* base = feats + (size_t)view * C_FEAT * HW
                                      + (size_t)v0 * WF + u0;
            float dot = 0.0f, nrm = 0.0f;
            #pragma unroll
            for (int i = 0; i < C_FEAT / 32; i++) {
                const int c = lane + i * 32;
                const float* pch = base + (size_t)c * HW;
                const float fm = 0.25f * (pch[0] + pch[1] + pch[WF] + pch[WF + 1]);
                dot += fm * s_stored[c];
                nrm += fm * fm;
            }
            #pragma unroll
            for (int o = 16; o > 0; o >>= 1) {
                dot += __shfl_xor_sync(0xffffffffu, dot, o);
                nrm += __shfl_xor_sync(0xffffffffu, nrm, o);
            }
            const float inv_i = 1.0f / fmaxf(sqrtf(nrm), EPS);
            loss = 1.0f - dot * inv_i * s_sinv;
            cnt = 1;
        }
        if (lane == 0) {
            s_loss[warp * 2 + j] = loss;
            s_lval[warp * 2 + j] = cnt;
        }
    }
    __syncthreads();

    // ---- Phase 4: deterministic block sum -> fixed-point global atomics ----
    if (tid == 0) {
        float bsum = 0.0f;
        int   bcnt = 0;
        #pragma unroll
        for (int k = 0; k < 16; k++) { bsum += s_loss[k]; bcnt += s_lval[k]; }
        const long long q = llrint((double)bsum * FSCALE);
        atomicAdd(&g_sum, (unsigned long long)q);
        atomicAdd(&g_cnt, bcnt);
        __threadfence();
        const int done = atomicAdd(&g_done, 1);
        if (done == NBLK - 1) {
            const long long tot = (long long)atomicAdd(&g_sum, 0ULL);
            const int n = atomicAdd(&g_cnt, 0);
            out[0] = (n > 0) ? (float)(((double)tot / FSCALE) / (double)n) : 0.0f;
            // reset for next replay (kernel boundary orders this vs next launch)
            g_sum = 0ULL; g_cnt = 0; g_done = 0;
        }
    }
}

extern "C" void kernel_launch(void* const* d_in, const int* in_sizes, int n_in,
                              void* d_out, int out_size)
{
    const float* boxes     = (const float*)d_in[0];  // (256, 7)
    const float* feats     = (const float*)d_in[1];  // (6, 256, 116, 200)
    const float* Kmat      = (const float*)d_in[2];  // (6, 3, 3)
    const float* Tmat      = (const float*)d_in[3];  // (6, 4, 4)
    const int*   img_sizes = (const int*)d_in[4];    // (6, 2)
    float* out = (float*)d_out;

    fused_kernel<<<NBLK, 256>>>(boxes, feats, Kmat, Tmat, img_sizes, out);
}